// round 3
// baseline (speedup 1.0000x reference)
#include <cuda_runtime.h>
#include <math.h>

#define NN   32      // batch
#define CIN  32      // input caps
#define CO   16      // output caps
#define PP   4
#define DD   16      // P*P
#define SSP  256     // W*H
#define MM   8192    // CIN*SSP

// ---- scratch (static device globals; no allocations) ----
__device__ float d_b  [NN*CO*MM];       // 16 MB  b[n][o][m], m = c*256+s
__device__ float d_S  [NN*CO*DD];       // routed sums
__device__ float d_mx [NN*CO];
__device__ float d_inv[NN*CO];
__device__ float d_Gp [NN*CIN*CO*DD];   // Gp[n][c][o][16]
__device__ float d_g  [NN*CO*DD];       // current g

// Gp[n,c,o,(i,j)] = sum_k W[c,o,(j,k)] * g[n,o,(i,k)]
__global__ void gp_kernel(const float* __restrict__ g_ext,
                          const float* __restrict__ w, int use_dev) {
    int tt = blockIdx.x * blockDim.x + threadIdx.x;   // 0..16383 = n*c*o
    int n   = tt / (CIN*CO);
    int rem = tt % (CIN*CO);
    int c   = rem / CO;
    int o   = rem % CO;
    const float* gs = use_dev ? d_g : g_ext;
    const float* gp = gs + (n*CO + o)*DD;
    const float* wp = w  + (c*CO + o)*DD;
    float gv[DD], wv[DD];
#pragma unroll
    for (int k = 0; k < DD; k++) { gv[k] = gp[k]; wv[k] = wp[k]; }
    float out[DD];
#pragma unroll
    for (int i = 0; i < PP; i++)
#pragma unroll
        for (int j = 0; j < PP; j++) {
            float a = 0.f;
#pragma unroll
            for (int k = 0; k < PP; k++) a += wv[j*PP + k] * gv[i*PP + k];
            out[i*PP + j] = a;
        }
    float* dst = d_Gp + tt*DD;
#pragma unroll
    for (int d = 0; d < DD; d++) dst[d] = out[d];
}

// b[n,o,c*256+s] (=|+=) sum_d l[n,c,d,s] * Gp[n,c,o,d]
template <bool ADD>
__global__ void b_kernel(const float* __restrict__ l) {
    __shared__ float gpsh[CO*DD];
    int bid = blockIdx.x;                 // n*CIN + c
    int n = bid >> 5, c = bid & 31;
    int s = threadIdx.x;                  // 256 threads
    gpsh[s] = d_Gp[bid*CO*DD + s];
    float lp[DD];
    const float* lb = l + (size_t)bid*DD*SSP + s;
#pragma unroll
    for (int d = 0; d < DD; d++) lp[d] = lb[d*SSP];
    __syncthreads();
#pragma unroll
    for (int o = 0; o < CO; o++) {
        float acc = 0.f;
#pragma unroll
        for (int d = 0; d < DD; d++) acc += lp[d] * gpsh[o*DD + d];
        float* bp = d_b + (size_t)(n*CO + o)*MM + c*SSP + s;
        if (ADD) *bp += acc; else *bp = acc;
    }
}

// per (n,o): max over m, 1/sum(exp), and zero S
__global__ void stats_kernel() {
    int bid = blockIdx.x;                 // n*CO + o  (contiguous b chunk)
    int t = threadIdx.x;                  // 256 threads
    const float* bp = d_b + (size_t)bid*MM;
    float vals[32];
    float lm = -1e30f;
#pragma unroll
    for (int j = 0; j < 32; j++) { vals[j] = bp[t + j*256]; lm = fmaxf(lm, vals[j]); }
#pragma unroll
    for (int off = 16; off > 0; off >>= 1)
        lm = fmaxf(lm, __shfl_xor_sync(0xffffffffu, lm, off));
    __shared__ float red[8];
    __shared__ float bc;
    if ((t & 31) == 0) red[t >> 5] = lm;
    __syncthreads();
    if (t == 0) {
        float m = red[0];
#pragma unroll
        for (int i = 1; i < 8; i++) m = fmaxf(m, red[i]);
        bc = m;
    }
    __syncthreads();
    float mx = bc;
    float ls = 0.f;
#pragma unroll
    for (int j = 0; j < 32; j++) ls += __expf(vals[j] - mx);
#pragma unroll
    for (int off = 16; off > 0; off >>= 1)
        ls += __shfl_xor_sync(0xffffffffu, ls, off);
    if ((t & 31) == 0) red[t >> 5] = ls;
    __syncthreads();
    if (t == 0) {
        float sm = 0.f;
#pragma unroll
        for (int i = 0; i < 8; i++) sm += red[i];
        d_mx[bid]  = mx;
        d_inv[bid] = 1.f / sm;
    }
    if (t < DD) d_S[bid*DD + t] = 0.f;
}

// T[n,c,o,(i,j)] = sum_s cc[n,c,s,o] * l[n,c,(i,j),s]; then U = T @ W[c,o]; atomic into S
__global__ void t_kernel(const float* __restrict__ l, const float* __restrict__ w) {
    __shared__ float lsh[DD*SSP];         // 16 KB
    int bid = blockIdx.x;                 // n*CIN + c
    int n = bid >> 5, c = bid & 31;
    int t = threadIdx.x;                  // 256 threads: t = o*16 + u
    const float* lb = l + (size_t)bid*DD*SSP;
    for (int i = t; i < DD*SSP; i += 256) lsh[i] = lb[i];
    int o = t >> 4, u = t & 15;
    float mx  = d_mx [n*CO + o];
    float inv = d_inv[n*CO + o];
    __syncthreads();
    float acc[DD];
#pragma unroll
    for (int d = 0; d < DD; d++) acc[d] = 0.f;
    const float* bp = d_b + (size_t)(n*CO + o)*MM + c*SSP + u;
#pragma unroll
    for (int k = 0; k < 16; k++) {
        int s = u + k*16;
        float cc = __expf(bp[k*16] - mx) * inv;
#pragma unroll
        for (int d = 0; d < DD; d++) acc[d] += cc * lsh[d*SSP + s];
    }
    // reduce across the 16 u-lanes (lanes 0-15 / 16-31 stay within their o)
#pragma unroll
    for (int off = 8; off > 0; off >>= 1)
#pragma unroll
        for (int d = 0; d < DD; d++)
            acc[d] += __shfl_down_sync(0xffffffffu, acc[d], off);
    if (u == 0) {
        float wv[DD];
        const float* wp = w + (c*CO + o)*DD;
#pragma unroll
        for (int d = 0; d < DD; d++) wv[d] = wp[d];
#pragma unroll
        for (int i = 0; i < PP; i++)
#pragma unroll
            for (int kk = 0; kk < PP; kk++) {
                float v = 0.f;
#pragma unroll
                for (int j = 0; j < PP; j++) v += acc[i*PP + j] * wv[j*PP + kk];
                atomicAdd(&d_S[(n*CO + o)*DD + i*PP + kk], v);
            }
    }
}

__global__ void squash_kernel(float* __restrict__ out_g) {
    int tt = blockIdx.x * blockDim.x + threadIdx.x;   // 0..511 = n*CO+o
    if (tt >= NN*CO) return;
    float v[DD]; float n2 = 0.f;
#pragma unroll
    for (int d = 0; d < DD; d++) { v[d] = d_S[tt*DD + d]; n2 += v[d]*v[d]; }
    float nn = sqrtf(n2);
    float sc = n2 / ((1.f + n2) * (nn + 1e-6f));
#pragma unroll
    for (int d = 0; d < DD; d++) {
        float gv = v[d] * sc;
        d_g[tt*DD + d] = gv;
        if (out_g) out_g[tt*DD + d] = gv;
    }
}

// a[n,m,o] = softmax(b)  -> contiguous float4 stores
__global__ void a_kernel(float* __restrict__ out_a) {
    int bid = blockIdx.x;                 // n*CIN + c
    int n = bid >> 5, c = bid & 31;
    int s = threadIdx.x;                  // 256 threads
    float a[CO];
#pragma unroll
    for (int o = 0; o < CO; o++) {
        float mx  = d_mx [n*CO + o];
        float inv = d_inv[n*CO + o];
        float bv  = d_b[(size_t)(n*CO + o)*MM + c*SSP + s];
        a[o] = __expf(bv - mx) * inv;
    }
    float4* dst = (float4*)(out_a + ((size_t)n*MM + c*SSP + s) * CO);
#pragma unroll
    for (int q = 0; q < 4; q++)
        dst[q] = make_float4(a[q*4], a[q*4+1], a[q*4+2], a[q*4+3]);
}

extern "C" void kernel_launch(void* const* d_in, const int* in_sizes, int n_in,
                              void* d_out, int out_size) {
    const float* l = (const float*)d_in[0];   // (32,32,16,16,16)
    const float* g = (const float*)d_in[1];   // (32,16,16)
    const float* w = (const float*)d_in[2];   // (1,32,1,16,4,4)
    // d_in[3] = num_iters (fixed = 3 by setup; not device-readable under capture)
    float* out_a = (float*)d_out;             // (32, 8192, 16)
    float* out_g = out_a + (size_t)NN*MM*CO;  // (32, 16, 16)

    const int NITERS = 3;

    gp_kernel<<<64, 256>>>(g, w, 0);          // Gp from input g
    b_kernel<false><<<NN*CIN, 256>>>(l);      // b init

    for (int it = 0; it < NITERS; it++) {
        stats_kernel<<<NN*CO, 256>>>();                       // softmax stats + zero S
        t_kernel<<<NN*CIN, 256>>>(l, w);                      // cc-weighted votes -> S
        squash_kernel<<<2, 256>>>(it == NITERS-1 ? out_g : nullptr);
        gp_kernel<<<64, 256>>>(nullptr, w, 1);                // Gp from new g
        if (it < NITERS - 1)
            b_kernel<true><<<NN*CIN, 256>>>(l);               // b += lp . Gp
        // last-iteration b update is dead code (a uses pre-update b)
    }
    a_kernel<<<NN*CIN, 256>>>(out_a);
}

// round 5
// speedup vs baseline: 1.5181x; 1.5181x over previous
#include <cuda_runtime.h>
#include <math.h>

#define NN   32
#define CIN  32
#define CO   16
#define DD   16
#define SSP  256
#define MM   8192

// ---- scratch ----
__device__ float d_b [NN*CO*MM];       // 16 MB: b[n][o][c*256+s]
__device__ float d_S [3*NN*CO*DD];     // triple-buffered routed sums
__device__ float d_pm[NN*CO*CIN];      // per-block softmax partial max   [n][o][c]
__device__ float d_ps[NN*CO*CIN];      // per-block softmax partial expsum

// Per-o block max + expsum partials from register-resident bb[16].
// Requires all 256 threads; uses redsh[128], mblk[16]; 3 syncthreads.
__device__ __forceinline__ void write_partials(const float bb[16], int n, int c, int t,
                                               float* redsh, float* mblk) {
    int lane = t & 31, warp = t >> 5;
    float wm[16];
#pragma unroll
    for (int o = 0; o < 16; o++) {
        float v = bb[o];
#pragma unroll
        for (int off = 16; off > 0; off >>= 1)
            v = fmaxf(v, __shfl_xor_sync(0xffffffffu, v, off));
        wm[o] = v;
    }
    if (lane == 0) {
#pragma unroll
        for (int o = 0; o < 16; o++) redsh[warp*16 + o] = wm[o];
    }
    __syncthreads();
    if (t < 16) {
        float m = redsh[t];
#pragma unroll
        for (int w = 1; w < 8; w++) m = fmaxf(m, redsh[w*16 + t]);
        mblk[t] = m;
    }
    __syncthreads();
    float ws[16];
#pragma unroll
    for (int o = 0; o < 16; o++) {
        float v = __expf(bb[o] - mblk[o]);
#pragma unroll
        for (int off = 16; off > 0; off >>= 1)
            v += __shfl_xor_sync(0xffffffffu, v, off);
        ws[o] = v;
    }
    if (lane == 0) {
#pragma unroll
        for (int o = 0; o < 16; o++) redsh[warp*16 + o] = ws[o];
    }
    __syncthreads();
    if (t < 16) {
        float s = 0.f;
#pragma unroll
        for (int w = 0; w < 8; w++) s += redsh[w*16 + t];
        d_pm[(n*16 + t)*32 + c] = mblk[t];
        d_ps[(n*16 + t)*32 + c] = s;
    }
}

// Gp[o, i*4+j] = sum_k W[c,o,j,k] * g[o, i*4+k]   (per-thread: one entry)
__device__ __forceinline__ void gp_compute(const float* wsh, const float* gsh,
                                           float* gpsh, int t) {
    int o = t >> 4, i = (t >> 2) & 3, j = t & 3;
    float a = 0.f;
#pragma unroll
    for (int k = 0; k < 4; k++)
        a += wsh[o*16 + j*4 + k] * gsh[o*16 + i*4 + k];
    gpsh[t] = a;
}

// bb[o] (+)= sum_d Gp[o,d]*lv[d], via float4 broadcast LDS
__device__ __forceinline__ void b_accum(float bb[16], const float4* gp4, const float lv[16]) {
#pragma unroll
    for (int o = 0; o < 16; o++) {
        float4 a0 = gp4[o*4+0], a1 = gp4[o*4+1], a2 = gp4[o*4+2], a3 = gp4[o*4+3];
        float acc = a0.x*lv[0] + a0.y*lv[1] + a0.z*lv[2] + a0.w*lv[3]
                  + a1.x*lv[4] + a1.y*lv[5] + a1.z*lv[6] + a1.w*lv[7]
                  + a2.x*lv[8] + a2.y*lv[9] + a2.z*lv[10]+ a2.w*lv[11]
                  + a3.x*lv[12]+ a3.y*lv[13]+ a3.z*lv[14]+ a3.w*lv[15];
        bb[o] += acc;
    }
}

// ---------- b init: Gp(g0) in-block, b = lp.Gp, partials; also zero all S ----------
__global__ void __launch_bounds__(256) binit_kernel(const float* __restrict__ l,
                                                    const float* __restrict__ g,
                                                    const float* __restrict__ w) {
    __shared__ float wsh[256], gsh[256];
    __shared__ __align__(16) float gpsh[256];
    __shared__ float redsh[128], mblk[16];
    int bid = blockIdx.x; int n = bid >> 5, c = bid & 31; int t = threadIdx.x;
    wsh[t] = w[c*256 + t];
    gsh[t] = g[n*256 + t];
    if (bid < 96) d_S[bid*256 + t] = 0.f;          // zero all 3 S buffers
    __syncthreads();
    gp_compute(wsh, gsh, gpsh, t);
    __syncthreads();
    float lv[16];
    const float* lb = l + (size_t)bid*4096 + t;
#pragma unroll
    for (int d = 0; d < 16; d++) lv[d] = lb[d*256];
    float bb[16];
#pragma unroll
    for (int o = 0; o < 16; o++) bb[o] = 0.f;
    b_accum(bb, (const float4*)gpsh, lv);
    size_t bbase = (size_t)n*131072 + c*256 + t;
#pragma unroll
    for (int o = 0; o < 16; o++) d_b[bbase + (size_t)o*8192] = bb[o];
    write_partials(bb, n, c, t, redsh, mblk);
}

// ---------- t: in-block stats merge, cc, tiled 16x16x256 matmul, W-mult, REDG to S ----------
template <bool LAST>
__global__ void __launch_bounds__(256) t_kernel(const float* __restrict__ l,
                                                const float* __restrict__ w,
                                                float* __restrict__ out_a, int sbuf) {
    __shared__ float lsh[256*17];
    __shared__ float csh[256*17];
    __shared__ float wsh[256];
    __shared__ float mxsh[16], invsh[16];
    __shared__ float tsh[16*17];
    int bid = blockIdx.x; int n = bid >> 5, c = bid & 31; int t = threadIdx.x;
    wsh[t] = w[c*256 + t];
    // merge softmax partials for this n (all 32 c) -> mx, 1/sum per o
    {
        int o = t >> 4, lane16 = t & 15;
        int base = (n*16 + o)*32;
        float m1 = d_pm[base + lane16],      s1 = d_ps[base + lane16];
        float m2 = d_pm[base + 16 + lane16], s2 = d_ps[base + 16 + lane16];
        float M = fmaxf(m1, m2);
        float S = s1*__expf(m1 - M) + s2*__expf(m2 - M);
#pragma unroll
        for (int off = 1; off < 16; off <<= 1) {
            float Mo = __shfl_xor_sync(0xffffffffu, M, off);
            float So = __shfl_xor_sync(0xffffffffu, S, off);
            float Mn = fmaxf(M, Mo);
            S = S*__expf(M - Mn) + So*__expf(Mo - Mn);
            M = Mn;
        }
        if (lane16 == 0) { mxsh[o] = M; invsh[o] = 1.f / S; }
    }
    // stage l (s-major, stride 17 -> conflict-free)
    {
        const float* lb = l + (size_t)bid*4096 + t;
#pragma unroll
        for (int d = 0; d < 16; d++) lsh[t*17 + d] = lb[d*256];
    }
    __syncthreads();
    // cc = softmax(b); stage s-major; last iter also writes a
    float cc[16];
    {
        size_t bbase = (size_t)n*131072 + c*256 + t;
#pragma unroll
        for (int o = 0; o < 16; o++) {
            float bv = d_b[bbase + (size_t)o*8192];
            cc[o] = __expf(bv - mxsh[o]) * invsh[o];
            csh[t*17 + o] = cc[o];
        }
        if (LAST) {
            float4* dst = (float4*)(out_a + ((size_t)bid*256 + t)*16);
            dst[0] = make_float4(cc[0], cc[1], cc[2], cc[3]);
            dst[1] = make_float4(cc[4], cc[5], cc[6], cc[7]);
            dst[2] = make_float4(cc[8], cc[9], cc[10], cc[11]);
            dst[3] = make_float4(cc[12], cc[13], cc[14], cc[15]);
        }
    }
    __syncthreads();
    // tiled matmul: T[o,d] = sum_s cc[o,s]*l[d,s]; thread = (og, dg, sc)
    {
        int sc = t & 15, dg = (t >> 4) & 3, og = t >> 6;
        float acc[16];
#pragma unroll
        for (int q = 0; q < 16; q++) acc[q] = 0.f;
#pragma unroll
        for (int k = 0; k < 16; k++) {
            int s = sc + 16*k;
            float c0 = csh[s*17 + og*4 + 0];
            float c1 = csh[s*17 + og*4 + 1];
            float c2 = csh[s*17 + og*4 + 2];
            float c3 = csh[s*17 + og*4 + 3];
            float l0 = lsh[s*17 + dg*4 + 0];
            float l1 = lsh[s*17 + dg*4 + 1];
            float l2 = lsh[s*17 + dg*4 + 2];
            float l3 = lsh[s*17 + dg*4 + 3];
            acc[0]  += c0*l0; acc[1]  += c0*l1; acc[2]  += c0*l2; acc[3]  += c0*l3;
            acc[4]  += c1*l0; acc[5]  += c1*l1; acc[6]  += c1*l2; acc[7]  += c1*l3;
            acc[8]  += c2*l0; acc[9]  += c2*l1; acc[10] += c2*l2; acc[11] += c2*l3;
            acc[12] += c3*l0; acc[13] += c3*l1; acc[14] += c3*l2; acc[15] += c3*l3;
        }
#pragma unroll
        for (int off = 1; off < 16; off <<= 1)
#pragma unroll
            for (int q = 0; q < 16; q++)
                acc[q] += __shfl_xor_sync(0xffffffffu, acc[q], off);
        if (sc == 0) {
#pragma unroll
            for (int oi = 0; oi < 4; oi++)
#pragma unroll
                for (int dj = 0; dj < 4; dj++)
                    tsh[(og*4 + oi)*17 + dg*4 + dj] = acc[oi*4 + dj];
        }
    }
    __syncthreads();
    // V[o, i*4+kk] = sum_j T[o, i*4+j] * W[c,o,j,kk]; atomic into S (addr == t)
    {
        int o = t >> 4, i = (t >> 2) & 3, kk = t & 3;
        float v = 0.f;
#pragma unroll
        for (int j = 0; j < 4; j++)
            v += tsh[o*17 + i*4 + j] * wsh[o*16 + j*4 + kk];
        atomicAdd(&d_S[sbuf*8192 + n*256 + t], v);
    }
}

// ---------- badd: squash(S) in-block, Gp, b += lp.Gp, new partials ----------
__global__ void __launch_bounds__(256) badd_kernel(const float* __restrict__ l,
                                                   const float* __restrict__ w, int sbuf) {
    __shared__ float wsh[256], gsh[256];
    __shared__ __align__(16) float gpsh[256];
    __shared__ float redsh[128], mblk[16];
    int bid = blockIdx.x; int n = bid >> 5, c = bid & 31; int t = threadIdx.x;
    wsh[t] = w[c*256 + t];
    // squash: g[o,d] from S[n,o,:]
    {
        float sv = d_S[sbuf*8192 + n*256 + t];
        float n2 = sv*sv;
#pragma unroll
        for (int off = 1; off < 16; off <<= 1)
            n2 += __shfl_xor_sync(0xffffffffu, n2, off);
        float nn = sqrtf(n2);
        gsh[t] = sv * (n2 / ((1.f + n2) * (nn + 1e-6f)));
    }
    __syncthreads();
    gp_compute(wsh, gsh, gpsh, t);
    __syncthreads();
    float lv[16];
    const float* lb = l + (size_t)bid*4096 + t;
#pragma unroll
    for (int d = 0; d < 16; d++) lv[d] = lb[d*256];
    size_t bbase = (size_t)n*131072 + c*256 + t;
    float bb[16];
#pragma unroll
    for (int o = 0; o < 16; o++) bb[o] = d_b[bbase + (size_t)o*8192];
    b_accum(bb, (const float4*)gpsh, lv);
#pragma unroll
    for (int o = 0; o < 16; o++) d_b[bbase + (size_t)o*8192] = bb[o];
    write_partials(bb, n, c, t, redsh, mblk);
}

// ---------- final g output ----------
__global__ void __launch_bounds__(256) squash_out_kernel(float* __restrict__ out_g, int sbuf) {
    int n = blockIdx.x; int t = threadIdx.x;
    float sv = d_S[sbuf*8192 + n*256 + t];
    float n2 = sv*sv;
#pragma unroll
    for (int off = 1; off < 16; off <<= 1)
        n2 += __shfl_xor_sync(0xffffffffu, n2, off);
    float nn = sqrtf(n2);
    out_g[n*256 + t] = sv * (n2 / ((1.f + n2) * (nn + 1e-6f)));
}

extern "C" void kernel_launch(void* const* d_in, const int* in_sizes, int n_in,
                              void* d_out, int out_size) {
    const float* l = (const float*)d_in[0];   // (32,32,16,16,16)
    const float* g = (const float*)d_in[1];   // (32,16,16)
    const float* w = (const float*)d_in[2];   // (1,32,1,16,4,4)
    float* out_a = (float*)d_out;             // (32, 8192, 16)
    float* out_g = out_a + (size_t)NN*MM*CO;  // (32, 16, 16)

    binit_kernel<<<NN*CIN, 256>>>(l, g, w);
    t_kernel<false><<<NN*CIN, 256>>>(l, w, nullptr, 0);   // iter 0
    badd_kernel<<<NN*CIN, 256>>>(l, w, 0);
    t_kernel<false><<<NN*CIN, 256>>>(l, w, nullptr, 1);   // iter 1
    badd_kernel<<<NN*CIN, 256>>>(l, w, 1);
    t_kernel<true><<<NN*CIN, 256>>>(l, w, out_a, 2);      // iter 2 (+a)
    squash_out_kernel<<<NN, 256>>>(out_g, 2);
}